// round 7
// baseline (speedup 1.0000x reference)
#include <cuda_runtime.h>
#include <cuda_fp16.h>
#include <cstdint>
#include <math.h>

// Problem constants
constexpr int B_ROWS = 8192;   // batch
constexpr int FDIM   = 4096;   // features
constexpr int NINT   = 511;    // internal nodes
constexpr int NPAD   = 512;    // padded internal dim
constexpr int NLEAF  = 512;
constexpr int KOUT   = 1000;
constexpr int NPAD2  = 1024;   // padded output-class dim

// Scratch (device globals; allocation is forbidden)
__device__ __half g_xh[(size_t)B_ROWS * FDIM];       // xs in fp16
__device__ __half g_wh[(size_t)NPAD * FDIM];         // W in fp16, row 511 zero
__device__ float  g_ps[(size_t)B_ROWS * NPAD];       // sigmoid(logits), fp32
__device__ __half g_lp[(size_t)B_ROWS * NLEAF];      // leaf probabilities, fp16
__device__ __half g_distsT[(size_t)NPAD2 * NLEAF];   // softmax(leaf_params)^T, rows 1000.. zero

// ---------------------------------------------------------------------------
// helpers
// ---------------------------------------------------------------------------
__device__ __forceinline__ uint32_t s2u(const void* p) {
    return (uint32_t)__cvta_generic_to_shared(p);
}

__device__ __forceinline__ void ldsm4(uint32_t* r, uint32_t addr) {
    asm volatile("ldmatrix.sync.aligned.m8n8.x4.shared.b16 {%0,%1,%2,%3}, [%4];"
        : "=r"(r[0]), "=r"(r[1]), "=r"(r[2]), "=r"(r[3]) : "r"(addr));
}

__device__ __forceinline__ void mma16(float* c, const uint32_t* a, uint32_t b0, uint32_t b1) {
    asm volatile(
        "mma.sync.aligned.m16n8k16.row.col.f32.f16.f16.f32 "
        "{%0,%1,%2,%3}, {%4,%5,%6,%7}, {%8,%9}, {%0,%1,%2,%3};\n"
        : "+f"(c[0]), "+f"(c[1]), "+f"(c[2]), "+f"(c[3])
        : "r"(a[0]), "r"(a[1]), "r"(a[2]), "r"(a[3]), "r"(b0), "r"(b1));
}

__device__ __forceinline__ void cpasync16(uint32_t dst, const void* src) {
    asm volatile("cp.async.cg.shared.global [%0], [%1], 16;" :: "r"(dst), "l"(src));
}
__device__ __forceinline__ void cp_commit() {
    asm volatile("cp.async.commit_group;" ::: "memory");
}
__device__ __forceinline__ void cp_wait1() {
    asm volatile("cp.async.wait_group 1;" ::: "memory");
}

// 64B rows (32 halves), chunk 0..3 of 16B — XOR swizzle (validated in R5)
__device__ __forceinline__ uint32_t sw64(int row, int chunk) {
    return row * 64 + ((chunk ^ ((row >> 1) & 3)) << 4);
}

// pack 8 fp32 -> 8 fp16 in a uint4
__device__ __forceinline__ uint4 pack8(float4 a, float4 b) {
    uint4 r;
    __half2 h;
    h = __floats2half2_rn(a.x, a.y); r.x = *(uint32_t*)&h;
    h = __floats2half2_rn(a.z, a.w); r.y = *(uint32_t*)&h;
    h = __floats2half2_rn(b.x, b.y); r.z = *(uint32_t*)&h;
    h = __floats2half2_rn(b.z, b.w); r.w = *(uint32_t*)&h;
    return r;
}

// ---------------------------------------------------------------------------
// Convert kernels (fp32 -> fp16)
// ---------------------------------------------------------------------------
__global__ void conv_x_kernel(const float* __restrict__ xs)
{
    const size_t i = ((size_t)blockIdx.x * 256 + threadIdx.x) * 8;
    const float4* s = (const float4*)(xs + i);
    *(uint4*)(g_xh + i) = pack8(s[0], s[1]);
}

__global__ void conv_w_kernel(const float* __restrict__ W)
{
    const size_t i = ((size_t)blockIdx.x * 256 + threadIdx.x) * 8;
    if (i < (size_t)NINT * FDIM) {
        const float4* s = (const float4*)(W + i);
        *(uint4*)(g_wh + i) = pack8(s[0], s[1]);
    } else {
        *(uint4*)(g_wh + i) = make_uint4(0, 0, 0, 0);
    }
}

__global__ void zerotail_kernel()
{
    // zero g_distsT rows [KOUT, NPAD2)
    g_distsT[(size_t)(KOUT + blockIdx.x) * NLEAF + threadIdx.x] = __float2half_rn(0.f);
}

// ---------------------------------------------------------------------------
// Shared GEMM core: CTA 128x128, 4 warps (64x64 warp tiles), BK=32 halves,
// cp.async 3-stage pipeline, fp16 m16n8k16, fp32 accum.
// A, B both K-major fp16 (rows of the K dim). Stage = 16KB (A 8KB + B 8KB).
// ---------------------------------------------------------------------------
#define GEMM_CORE(Aptr, Astride, Bptr, Bstride, KT)                              \
    __shared__ __align__(16) char smem[3 * 16384];                                \
    const uint32_t sb = s2u(smem);                                                \
    const int tid = threadIdx.x, warp = tid >> 5, lane = tid & 31;                \
    const int wm = warp & 1, wn = warp >> 1;                                      \
    const int tn = blockIdx.x, tm = blockIdx.y;                                   \
    float c[4][8][4];                                                             \
    _Pragma("unroll")                                                             \
    for (int i = 0; i < 4; i++)                                                   \
        _Pragma("unroll")                                                         \
        for (int j = 0; j < 8; j++)                                               \
            _Pragma("unroll")                                                     \
            for (int k = 0; k < 4; k++) c[i][j][k] = 0.f;                         \
    const __half* Ag = (Aptr) + (size_t)(tm * 128 + tid) * (Astride);             \
    const __half* Bg = (Bptr) + (size_t)(tn * 128 + tid) * (Bstride);             \
    auto issue = [&](int kt) {                                                    \
        if (kt < (KT)) {                                                          \
            const uint32_t Ab = sb + (kt % 3) * 16384;                            \
            const uint32_t Bb = Ab + 8192;                                        \
            const __half* ag = Ag + kt * 32;                                      \
            const __half* bg = Bg + kt * 32;                                      \
            _Pragma("unroll")                                                     \
            for (int ch = 0; ch < 4; ch++)                                        \
                cpasync16(Ab + sw64(tid, ch), ag + ch * 8);                       \
            _Pragma("unroll")                                                     \
            for (int ch = 0; ch < 4; ch++)                                        \
                cpasync16(Bb + sw64(tid, ch), bg + ch * 8);                       \
        }                                                                         \
        cp_commit();                                                              \
    };                                                                            \
    auto compute = [&](int buf) {                                                 \
        const uint32_t Ab = sb + buf * 16384;                                     \
        const uint32_t Bb = Ab + 8192;                                            \
        _Pragma("unroll")                                                         \
        for (int ks = 0; ks < 2; ks++) {                                          \
            const int kc = ks * 2 + (lane >> 4);                                  \
            uint32_t a[4][4], b[4][4];                                            \
            _Pragma("unroll")                                                     \
            for (int mt = 0; mt < 4; mt++)                                        \
                ldsm4(a[mt], Ab + sw64(wm * 64 + mt * 16 + (lane & 15), kc));     \
            _Pragma("unroll")                                                     \
            for (int nt = 0; nt < 4; nt++)                                        \
                ldsm4(b[nt], Bb + sw64(wn * 64 + nt * 16 + (lane & 15), kc));     \
            _Pragma("unroll")                                                     \
            for (int mt = 0; mt < 4; mt++)                                        \
                _Pragma("unroll")                                                 \
                for (int nt = 0; nt < 4; nt++) {                                  \
                    mma16(c[mt][nt * 2],     a[mt], b[nt][0], b[nt][2]);          \
                    mma16(c[mt][nt * 2 + 1], a[mt], b[nt][1], b[nt][3]);          \
                }                                                                 \
        }                                                                         \
    };                                                                            \
    issue(0);                                                                     \
    issue(1);                                                                     \
    for (int kt = 0; kt < (KT); kt++) {                                           \
        cp_wait1();                                                               \
        __syncthreads();                                                          \
        compute(kt % 3);                                                          \
        issue(kt + 2);                                                            \
    }

// ---------------------------------------------------------------------------
// GEMM1: ps = sigmoid(xh @ wh^T + b)   grid (4, 64), 128 threads
// ---------------------------------------------------------------------------
__global__ __launch_bounds__(128, 2)
void gemm1_kernel(const float* __restrict__ bias)
{
    GEMM_CORE(g_xh, FDIM, g_wh, FDIM, FDIM / 32)

    const int g = lane >> 2, tg = lane & 3;
    #pragma unroll
    for (int mt = 0; mt < 4; mt++) {
        #pragma unroll
        for (int j = 0; j < 8; j++) {
            const int col = tn * 128 + wn * 64 + j * 8 + 2 * tg;
            const float bb0 = (col     < NINT) ? __ldg(bias + col)     : 0.f;
            const float bb1 = (col + 1 < NINT) ? __ldg(bias + col + 1) : 0.f;
            const int row0 = tm * 128 + wm * 64 + mt * 16 + g;
            float v0 = c[mt][j][0] + bb0;
            float v1 = c[mt][j][1] + bb1;
            float v2 = c[mt][j][2] + bb0;
            float v3 = c[mt][j][3] + bb1;
            float2 p0 = make_float2(1.f / (1.f + __expf(-v0)), 1.f / (1.f + __expf(-v1)));
            float2 p1 = make_float2(1.f / (1.f + __expf(-v2)), 1.f / (1.f + __expf(-v3)));
            *(float2*)&g_ps[(size_t)row0       * NPAD + col] = p0;
            *(float2*)&g_ps[(size_t)(row0 + 8) * NPAD + col] = p1;
        }
    }
}

// ---------------------------------------------------------------------------
// GEMM2: out = leaf_prob[8192,512] @ distsT^T[512,1024]   grid (8, 64)
// ---------------------------------------------------------------------------
__global__ __launch_bounds__(128, 2)
void gemm2_kernel(float* __restrict__ out)
{
    GEMM_CORE(g_lp, NLEAF, g_distsT, NLEAF, NLEAF / 32)

    const int g = lane >> 2, tg = lane & 3;
    #pragma unroll
    for (int mt = 0; mt < 4; mt++) {
        #pragma unroll
        for (int j = 0; j < 8; j++) {
            const int col = tn * 128 + wn * 64 + j * 8 + 2 * tg;
            if (col < KOUT) {   // col even, KOUT even -> pair in-bounds
                const int row0 = tm * 128 + wm * 64 + mt * 16 + g;
                *(float2*)&out[(size_t)row0       * KOUT + col] =
                    make_float2(c[mt][j][0], c[mt][j][1]);
                *(float2*)&out[(size_t)(row0 + 8) * KOUT + col] =
                    make_float2(c[mt][j][2], c[mt][j][3]);
            }
        }
    }
}

// ---------------------------------------------------------------------------
// Leaf probabilities: one block per row, 512 threads (one per leaf), fp16 out
// ---------------------------------------------------------------------------
__global__ void leaf_kernel()
{
    __shared__ float sp[NINT];
    const int row = blockIdx.x;
    const int j = threadIdx.x;
    if (j < NINT) sp[j] = g_ps[(size_t)row * NPAD + j];
    __syncthreads();
    float prod = 1.f;
    int node = 0;
    #pragma unroll
    for (int t = 0; t < 9; t++) {
        const int bit = (j >> (8 - t)) & 1;
        const float p = sp[node];
        prod *= bit ? p : (1.f - p);
        node = 2 * node + 1 + bit;
    }
    g_lp[(size_t)row * NLEAF + j] = __float2half_rn(prod);
}

// ---------------------------------------------------------------------------
// Softmax over leaf_params rows -> g_distsT[class][leaf] (fp16, transposed)
// ---------------------------------------------------------------------------
__global__ void softmax_kernel(const float* __restrict__ lp)
{
    const int row = blockIdx.x;       // leaf
    const int tid = threadIdx.x;
    const float* src = lp + (size_t)row * KOUT;
    __shared__ float red[8];

    float m = -1e30f;
    for (int i = tid; i < KOUT; i += 256) m = fmaxf(m, src[i]);
    #pragma unroll
    for (int o = 16; o > 0; o >>= 1) m = fmaxf(m, __shfl_xor_sync(0xffffffffu, m, o));
    if ((tid & 31) == 0) red[tid >> 5] = m;
    __syncthreads();
    if (tid < 32) {
        float v = (tid < 8) ? red[tid] : -1e30f;
        #pragma unroll
        for (int o = 4; o > 0; o >>= 1) v = fmaxf(v, __shfl_xor_sync(0xffffffffu, v, o));
        if (tid == 0) red[0] = v;
    }
    __syncthreads();
    m = red[0];
    __syncthreads();

    float s = 0.f;
    for (int i = tid; i < KOUT; i += 256) s += __expf(src[i] - m);
    #pragma unroll
    for (int o = 16; o > 0; o >>= 1) s += __shfl_xor_sync(0xffffffffu, s, o);
    if ((tid & 31) == 0) red[tid >> 5] = s;
    __syncthreads();
    if (tid < 32) {
        float v = (tid < 8) ? red[tid] : 0.f;
        #pragma unroll
        for (int o = 4; o > 0; o >>= 1) v += __shfl_xor_sync(0xffffffffu, v, o);
        if (tid == 0) red[0] = v;
    }
    __syncthreads();
    const float inv = 1.f / red[0];
    for (int i = tid; i < KOUT; i += 256)
        g_distsT[(size_t)i * NLEAF + row] = __float2half_rn(__expf(src[i] - m) * inv);
}

// ---------------------------------------------------------------------------
// Launch
// ---------------------------------------------------------------------------
extern "C" void kernel_launch(void* const* d_in, const int* in_sizes, int n_in,
                              void* d_out, int out_size)
{
    const float* xs          = (const float*)d_in[0];   // [8192, 4096]
    const float* W           = (const float*)d_in[1];   // [511, 4096]
    const float* b           = (const float*)d_in[2];   // [511]
    const float* leaf_params = (const float*)d_in[3];   // [512, 1000]
    float* out = (float*)d_out;                         // [8192, 1000]

    conv_x_kernel<<<(B_ROWS * FDIM) / (256 * 8), 256>>>(xs);
    conv_w_kernel<<<(NPAD * FDIM) / (256 * 8), 256>>>(W);
    softmax_kernel<<<NLEAF, 256>>>(leaf_params);
    zerotail_kernel<<<NPAD2 - KOUT, NLEAF>>>();
    gemm1_kernel<<<dim3(4, 64), 128>>>(b);
    leaf_kernel<<<B_ROWS, 512>>>();
    gemm2_kernel<<<dim3(8, 64), 128>>>(out);
}

// round 8
// speedup vs baseline: 1.3972x; 1.3972x over previous
#include <cuda_runtime.h>
#include <cuda_fp16.h>
#include <cstdint>
#include <math.h>

// Problem constants
constexpr int B_ROWS = 8192;   // batch
constexpr int FDIM   = 4096;   // features
constexpr int NINT   = 511;    // internal nodes
constexpr int NPAD   = 512;    // padded internal dim
constexpr int NLEAF  = 512;
constexpr int KOUT   = 1000;
constexpr int NPAD2  = 1024;   // padded output-class dim

// Scratch (device globals; allocation is forbidden)
__device__ __half g_xh[(size_t)B_ROWS * FDIM];       // xs in fp16
__device__ __half g_wh[(size_t)NPAD * FDIM];         // W in fp16, row 511 zero
__device__ float  g_ps[(size_t)B_ROWS * NPAD];       // sigmoid(logits), fp32
__device__ __half g_lp[(size_t)B_ROWS * NLEAF];      // leaf probabilities, fp16
__device__ __half g_distsT[(size_t)NPAD2 * NLEAF];   // softmax(leaf_params)^T, rows 1000.. zero

// ---------------------------------------------------------------------------
// helpers
// ---------------------------------------------------------------------------
__device__ __forceinline__ uint32_t s2u(const void* p) {
    return (uint32_t)__cvta_generic_to_shared(p);
}

__device__ __forceinline__ void ldsm4(uint32_t* r, uint32_t addr) {
    asm volatile("ldmatrix.sync.aligned.m8n8.x4.shared.b16 {%0,%1,%2,%3}, [%4];"
        : "=r"(r[0]), "=r"(r[1]), "=r"(r[2]), "=r"(r[3]) : "r"(addr));
}

__device__ __forceinline__ void mma16(float* c, const uint32_t* a, uint32_t b0, uint32_t b1) {
    asm volatile(
        "mma.sync.aligned.m16n8k16.row.col.f32.f16.f16.f32 "
        "{%0,%1,%2,%3}, {%4,%5,%6,%7}, {%8,%9}, {%0,%1,%2,%3};\n"
        : "+f"(c[0]), "+f"(c[1]), "+f"(c[2]), "+f"(c[3])
        : "r"(a[0]), "r"(a[1]), "r"(a[2]), "r"(a[3]), "r"(b0), "r"(b1));
}

__device__ __forceinline__ void cpasync16(uint32_t dst, const void* src) {
    asm volatile("cp.async.cg.shared.global [%0], [%1], 16;" :: "r"(dst), "l"(src));
}
__device__ __forceinline__ void cp_commit() {
    asm volatile("cp.async.commit_group;" ::: "memory");
}
__device__ __forceinline__ void cp_wait1() {
    asm volatile("cp.async.wait_group 1;" ::: "memory");
}

// 64B rows (32 halves), chunk 0..3 of 16B — XOR swizzle (validated R5)
__device__ __forceinline__ uint32_t sw64(int row, int chunk) {
    return row * 64 + ((chunk ^ ((row >> 1) & 3)) << 4);
}

// pack 8 fp32 -> 8 fp16 in a uint4
__device__ __forceinline__ uint4 pack8(float4 a, float4 b) {
    uint4 r;
    __half2 h;
    h = __floats2half2_rn(a.x, a.y); r.x = *(uint32_t*)&h;
    h = __floats2half2_rn(a.z, a.w); r.y = *(uint32_t*)&h;
    h = __floats2half2_rn(b.x, b.y); r.z = *(uint32_t*)&h;
    h = __floats2half2_rn(b.z, b.w); r.w = *(uint32_t*)&h;
    return r;
}

// ---------------------------------------------------------------------------
// Convert kernels (fp32 -> fp16)
// ---------------------------------------------------------------------------
__global__ void conv_x_kernel(const float* __restrict__ xs)
{
    const size_t i = ((size_t)blockIdx.x * 256 + threadIdx.x) * 8;
    const float4* s = (const float4*)(xs + i);
    *(uint4*)(g_xh + i) = pack8(s[0], s[1]);
}

__global__ void conv_w_kernel(const float* __restrict__ W)
{
    const size_t i = ((size_t)blockIdx.x * 256 + threadIdx.x) * 8;
    if (i < (size_t)NINT * FDIM) {
        const float4* s = (const float4*)(W + i);
        *(uint4*)(g_wh + i) = pack8(s[0], s[1]);
    } else {
        *(uint4*)(g_wh + i) = make_uint4(0, 0, 0, 0);
    }
}

__global__ void zerotail_kernel()
{
    g_distsT[(size_t)(KOUT + blockIdx.x) * NLEAF + threadIdx.x] = __float2half_rn(0.f);
}

// ---------------------------------------------------------------------------
// Shared GEMM core: CTA 128x128, 8 warps (32x64 warp tiles, R5-proven),
// BK=32 halves, 3-stage cp.async pipeline, fp16 m16n8k16, fp32 accum.
// A, B both K-major fp16 rows (B padded -> guard-free mainloop).
// Stage = 16KB (A 8KB + B 8KB); 3 stages = 48KB static smem; 2 CTAs/SM.
// Pipeline order per iter: wait(oldest) -> sync -> issue(kt+2) -> compute(kt).
//   buffers: compute kt%3, in-flight (kt+1)%3 and (kt+2)%3 — all distinct;
//   the sync before issue guarantees no warp still reads the reused buffer.
// ---------------------------------------------------------------------------
#define GEMM_CORE(Aptr, Astride, Bptr, Bstride, KT)                              \
    __shared__ __align__(16) char smem[3 * 16384];                                \
    const uint32_t sb = s2u(smem);                                                \
    const int tid = threadIdx.x, warp = tid >> 5, lane = tid & 31;                \
    const int wm = warp & 3, wn = warp >> 2;                                      \
    const int tn = blockIdx.x, tm = blockIdx.y;                                   \
    float c[2][8][4];                                                             \
    _Pragma("unroll")                                                             \
    for (int i = 0; i < 2; i++)                                                   \
        _Pragma("unroll")                                                         \
        for (int j = 0; j < 8; j++)                                               \
            _Pragma("unroll")                                                     \
            for (int k = 0; k < 4; k++) c[i][j][k] = 0.f;                         \
    const int lrow = tid >> 1, lch = (tid & 1) * 2;                               \
    const __half* Ag = (Aptr) + (size_t)(tm * 128 + lrow) * (Astride) + (tid & 1) * 16; \
    const __half* Bg = (Bptr) + (size_t)(tn * 128 + lrow) * (Bstride) + (tid & 1) * 16; \
    auto issue = [&](int kt) {                                                    \
        if (kt < (KT)) {                                                          \
            const uint32_t Ab = sb + (kt % 3) * 16384;                            \
            const __half* ag = Ag + kt * 32;                                      \
            const __half* bg = Bg + kt * 32;                                      \
            cpasync16(Ab + sw64(lrow, lch),            ag);                       \
            cpasync16(Ab + sw64(lrow, lch + 1),        ag + 8);                   \
            cpasync16(Ab + 8192 + sw64(lrow, lch),     bg);                       \
            cpasync16(Ab + 8192 + sw64(lrow, lch + 1), bg + 8);                   \
        }                                                                         \
        cp_commit();                                                              \
    };                                                                            \
    auto compute = [&](int buf) {                                                 \
        const uint32_t Ab = sb + buf * 16384;                                     \
        const uint32_t Bb = Ab + 8192;                                            \
        _Pragma("unroll")                                                         \
        for (int ks = 0; ks < 2; ks++) {                                          \
            const int kc = ks * 2 + (lane >> 4);                                  \
            uint32_t a[2][4], b[4][4];                                            \
            _Pragma("unroll")                                                     \
            for (int mt = 0; mt < 2; mt++)                                        \
                ldsm4(a[mt], Ab + sw64(wm * 32 + mt * 16 + (lane & 15), kc));     \
            _Pragma("unroll")                                                     \
            for (int nt = 0; nt < 4; nt++)                                        \
                ldsm4(b[nt], Bb + sw64(wn * 64 + nt * 16 + (lane & 15), kc));     \
            _Pragma("unroll")                                                     \
            for (int mt = 0; mt < 2; mt++)                                        \
                _Pragma("unroll")                                                 \
                for (int nt = 0; nt < 4; nt++) {                                  \
                    mma16(c[mt][nt * 2],     a[mt], b[nt][0], b[nt][2]);          \
                    mma16(c[mt][nt * 2 + 1], a[mt], b[nt][1], b[nt][3]);          \
                }                                                                 \
        }                                                                         \
    };                                                                            \
    issue(0);                                                                     \
    issue(1);                                                                     \
    for (int kt = 0; kt < (KT); kt++) {                                           \
        cp_wait1();                                                               \
        __syncthreads();                                                          \
        issue(kt + 2);                                                            \
        compute(kt % 3);                                                          \
    }

// ---------------------------------------------------------------------------
// GEMM1: ps = sigmoid(xh @ wh^T + b)   grid (4, 64), 256 threads
// ---------------------------------------------------------------------------
__global__ __launch_bounds__(256, 2)
void gemm1_kernel(const float* __restrict__ bias)
{
    GEMM_CORE(g_xh, FDIM, g_wh, FDIM, FDIM / 32)

    const int g = lane >> 2, tg = lane & 3;
    #pragma unroll
    for (int mt = 0; mt < 2; mt++) {
        #pragma unroll
        for (int j = 0; j < 8; j++) {
            const int col = tn * 128 + wn * 64 + j * 8 + 2 * tg;
            const float bb0 = (col     < NINT) ? __ldg(bias + col)     : 0.f;
            const float bb1 = (col + 1 < NINT) ? __ldg(bias + col + 1) : 0.f;
            const int row0 = tm * 128 + wm * 32 + mt * 16 + g;
            float v0 = c[mt][j][0] + bb0;
            float v1 = c[mt][j][1] + bb1;
            float v2 = c[mt][j][2] + bb0;
            float v3 = c[mt][j][3] + bb1;
            float2 p0 = make_float2(1.f / (1.f + __expf(-v0)), 1.f / (1.f + __expf(-v1)));
            float2 p1 = make_float2(1.f / (1.f + __expf(-v2)), 1.f / (1.f + __expf(-v3)));
            *(float2*)&g_ps[(size_t)row0       * NPAD + col] = p0;
            *(float2*)&g_ps[(size_t)(row0 + 8) * NPAD + col] = p1;
        }
    }
}

// ---------------------------------------------------------------------------
// GEMM2: out = leaf_prob[8192,512] @ distsT^T[512, 1024pad]   grid (8, 64)
// ---------------------------------------------------------------------------
__global__ __launch_bounds__(256, 2)
void gemm2_kernel(float* __restrict__ out)
{
    GEMM_CORE(g_lp, NLEAF, g_distsT, NLEAF, NLEAF / 32)

    const int g = lane >> 2, tg = lane & 3;
    #pragma unroll
    for (int mt = 0; mt < 2; mt++) {
        #pragma unroll
        for (int j = 0; j < 8; j++) {
            const int col = tn * 128 + wn * 64 + j * 8 + 2 * tg;
            if (col < KOUT) {   // col even, KOUT even -> pair in-bounds
                const int row0 = tm * 128 + wm * 32 + mt * 16 + g;
                *(float2*)&out[(size_t)row0       * KOUT + col] =
                    make_float2(c[mt][j][0], c[mt][j][1]);
                *(float2*)&out[(size_t)(row0 + 8) * KOUT + col] =
                    make_float2(c[mt][j][2], c[mt][j][3]);
            }
        }
    }
}

// ---------------------------------------------------------------------------
// Leaf probabilities: one block per row, 512 threads (one per leaf), fp16 out
// ---------------------------------------------------------------------------
__global__ void leaf_kernel()
{
    __shared__ float sp[NINT];
    const int row = blockIdx.x;
    const int j = threadIdx.x;
    if (j < NINT) sp[j] = g_ps[(size_t)row * NPAD + j];
    __syncthreads();
    float prod = 1.f;
    int node = 0;
    #pragma unroll
    for (int t = 0; t < 9; t++) {
        const int bit = (j >> (8 - t)) & 1;
        const float p = sp[node];
        prod *= bit ? p : (1.f - p);
        node = 2 * node + 1 + bit;
    }
    g_lp[(size_t)row * NLEAF + j] = __float2half_rn(prod);
}

// ---------------------------------------------------------------------------
// Softmax over leaf_params rows -> g_distsT[class][leaf] (fp16, transposed)
// ---------------------------------------------------------------------------
__global__ void softmax_kernel(const float* __restrict__ lp)
{
    const int row = blockIdx.x;       // leaf
    const int tid = threadIdx.x;
    const float* src = lp + (size_t)row * KOUT;
    __shared__ float red[8];

    float m = -1e30f;
    for (int i = tid; i < KOUT; i += 256) m = fmaxf(m, src[i]);
    #pragma unroll
    for (int o = 16; o > 0; o >>= 1) m = fmaxf(m, __shfl_xor_sync(0xffffffffu, m, o));
    if ((tid & 31) == 0) red[tid >> 5] = m;
    __syncthreads();
    if (tid < 32) {
        float v = (tid < 8) ? red[tid] : -1e30f;
        #pragma unroll
        for (int o = 4; o > 0; o >>= 1) v = fmaxf(v, __shfl_xor_sync(0xffffffffu, v, o));
        if (tid == 0) red[0] = v;
    }
    __syncthreads();
    m = red[0];
    __syncthreads();

    float s = 0.f;
    for (int i = tid; i < KOUT; i += 256) s += __expf(src[i] - m);
    #pragma unroll
    for (int o = 16; o > 0; o >>= 1) s += __shfl_xor_sync(0xffffffffu, s, o);
    if ((tid & 31) == 0) red[tid >> 5] = s;
    __syncthreads();
    if (tid < 32) {
        float v = (tid < 8) ? red[tid] : 0.f;
        #pragma unroll
        for (int o = 4; o > 0; o >>= 1) v += __shfl_xor_sync(0xffffffffu, v, o);
        if (tid == 0) red[0] = v;
    }
    __syncthreads();
    const float inv = 1.f / red[0];
    for (int i = tid; i < KOUT; i += 256)
        g_distsT[(size_t)i * NLEAF + row] = __float2half_rn(__expf(src[i] - m) * inv);
}

// ---------------------------------------------------------------------------
// Launch
// ---------------------------------------------------------------------------
extern "C" void kernel_launch(void* const* d_in, const int* in_sizes, int n_in,
                              void* d_out, int out_size)
{
    const float* xs          = (const float*)d_in[0];   // [8192, 4096]
    const float* W           = (const float*)d_in[1];   // [511, 4096]
    const float* b           = (const float*)d_in[2];   // [511]
    const float* leaf_params = (const float*)d_in[3];   // [512, 1000]
    float* out = (float*)d_out;                         // [8192, 1000]

    conv_x_kernel<<<(B_ROWS * FDIM) / (256 * 8), 256>>>(xs);
    conv_w_kernel<<<(NPAD * FDIM) / (256 * 8), 256>>>(W);
    softmax_kernel<<<NLEAF, 256>>>(leaf_params);
    zerotail_kernel<<<NPAD2 - KOUT, NLEAF>>>();
    gemm1_kernel<<<dim3(4, 64), 256>>>(b);
    leaf_kernel<<<B_ROWS, 512>>>();
    gemm2_kernel<<<dim3(8, 64), 256>>>(out);
}